// round 2
// baseline (speedup 1.0000x reference)
#include <cuda_runtime.h>

#define BB 64
#define TT 577
#define DD 768
#define DENS 519      // int(577*0.9)
#define NSKIP 58      // 577 - 519
#define D4 (DD/4)     // 192 float4 per row

// Scratch (no allocation allowed in kernel_launch)
__device__ float g_logits[BB*TT];
__device__ int   g_order[BB*TT];     // per batch: [0,519) = tokens order (desc), [519,577) = skip order (asc)
__device__ float g_weights[BB*NSKIP];

// ---------------- Kernel 1: logits = x @ w + b  (one warp per row) ----------------
__global__ void logits_kernel(const float* __restrict__ x,
                              const float* __restrict__ w,
                              const float* __restrict__ bias) {
    int warpsPerBlock = blockDim.x >> 5;
    int warpId = threadIdx.x >> 5;
    int lane   = threadIdx.x & 31;
    int row = blockIdx.x * warpsPerBlock + warpId;
    if (row >= BB*TT) return;

    const float4* xr = reinterpret_cast<const float4*>(x) + (size_t)row * D4;
    const float4* w4 = reinterpret_cast<const float4*>(w);

    float acc = 0.f;
    #pragma unroll
    for (int k = 0; k < 6; k++) {           // 6*32 = 192 float4
        float4 a  = xr[k*32 + lane];
        float4 wv = __ldg(&w4[k*32 + lane]);
        acc = fmaf(a.x, wv.x, acc);
        acc = fmaf(a.y, wv.y, acc);
        acc = fmaf(a.z, wv.z, acc);
        acc = fmaf(a.w, wv.w, acc);
    }
    #pragma unroll
    for (int off = 16; off; off >>= 1)
        acc += __shfl_xor_sync(0xffffffffu, acc, off);
    if (lane == 0) g_logits[row] = acc + bias[0];
}

// ---------------- Kernel 2: rank (stable top-k order) + skip softmax ----------------
__global__ void rank_kernel() {
    __shared__ float s[TT];
    __shared__ float skipP[NSKIP];
    __shared__ float skipE[NSKIP];

    int b = blockIdx.x;
    int i = threadIdx.x;

    if (i < TT) s[i] = g_logits[b*TT + i];
    __syncthreads();

    if (i < TT) {
        float my = s[i];
        int rank = 0;
        #pragma unroll 8
        for (int j = 0; j < TT; j++) {
            float v = s[j];
            rank += (v > my) || (v == my && j < i);  // stable: lower index wins
        }
        if (rank < DENS) {
            g_order[b*TT + rank] = i;                // descending kept tokens
        } else {
            int pos = (TT - 1) - rank;               // ascending skipped tokens
            g_order[b*TT + DENS + pos] = i;
            skipP[pos] = 1.f / (1.f + expf(-my));    // sigmoid prob
        }
    }
    __syncthreads();

    if (i < NSKIP) {
        float m = -1e30f;
        #pragma unroll
        for (int j = 0; j < NSKIP; j++) m = fmaxf(m, skipP[j]);
        skipE[i] = expf(skipP[i] - m);
    }
    __syncthreads();

    if (i < NSKIP) {
        float sum = 0.f;
        #pragma unroll
        for (int j = 0; j < NSKIP; j++) sum += skipE[j];
        g_weights[b*NSKIP + i] = skipE[i] / sum;
    }
}

// ---------------- Kernel 3: gather tokens/skip + weighted summary ----------------
__global__ void gather_kernel(const float* __restrict__ x, float* __restrict__ out) {
    int idx = blockIdx.x;           // [0, BB*(TT+1))
    int b = idx / (TT + 1);
    int t = idx - b * (TT + 1);
    int tid = threadIdx.x;          // 0..191 (float4 lanes)

    const float4* xin = reinterpret_cast<const float4*>(x);
    float4* o4 = reinterpret_cast<float4*>(out);

    const size_t skipBase = (size_t)BB * DENS * D4;
    const size_t sumBase  = skipBase + (size_t)BB * NSKIP * D4;

    if (t < TT) {
        int src = g_order[b*TT + t];
        float4 v = xin[((size_t)b*TT + src) * D4 + tid];
        size_t off = (t < DENS)
            ? ((size_t)(b*DENS + t) * D4)
            : (skipBase + (size_t)(b*NSKIP + (t - DENS)) * D4);
        o4[off + tid] = v;
    } else {
        // summary token: weighted sum of the 58 skipped rows
        float4 acc = make_float4(0.f, 0.f, 0.f, 0.f);
        #pragma unroll 2
        for (int sI = 0; sI < NSKIP; sI++) {
            int src = g_order[b*TT + DENS + sI];
            float wgt = g_weights[b*NSKIP + sI];
            float4 v = xin[((size_t)b*TT + src) * D4 + tid];
            acc.x = fmaf(wgt, v.x, acc.x);
            acc.y = fmaf(wgt, v.y, acc.y);
            acc.z = fmaf(wgt, v.z, acc.z);
            acc.w = fmaf(wgt, v.w, acc.w);
        }
        o4[sumBase + (size_t)b * D4 + tid] = acc;
    }
}

extern "C" void kernel_launch(void* const* d_in, const int* in_sizes, int n_in,
                              void* d_out, int out_size) {
    const float* x    = (const float*)d_in[0];
    const float* w    = (const float*)d_in[1];
    const float* bias = (const float*)d_in[2];
    float* out = (float*)d_out;

    // 1) logits: 36928 rows, 8 warps/block
    int rows = BB * TT;
    logits_kernel<<<(rows + 7) / 8, 256>>>(x, w, bias);

    // 2) rank + softmax: one block per batch (19 warps covers 577 threads)
    rank_kernel<<<BB, 608>>>();

    // 3) gather + summary: one block per output row
    gather_kernel<<<BB * (TT + 1), 192>>>(x, out);
}